// round 12
// baseline (speedup 1.0000x reference)
#include <cuda_runtime.h>
#include <cuda_bf16.h>
#include <math.h>
#include <stdint.h>

// Problem constants
#define Bb   8
#define Cc   256
#define Hh   64
#define Ww   64
#define NQ   4096           // H*W
#define NPIX (Bb*NQ)        // 32768
#define NHh  4
#define NPp  4
#define Dd   64
#define EPSf 1e-5f

// ---------------- scratch (static device globals; no allocation) ----------------
__device__ float g_mean1[NPIX], g_rstd1[NPIX], g_mean2[NPIX], g_rstd2[NPIX];
__device__ float g_qp[NQ * 48];          // qpos @ [W_off | W_att]
__device__ float g_c48[48];              // b + ln1_b @ W
__device__ float g_gs48[48];             // ln1_g @ W
__device__ float g_vG[Cc];               // ln2_g @ W_val
__device__ float g_vc[Cc];               // b_val + ln2_b @ W_val
__device__ uint32_t g_x1b[(size_t)NPIX * 128];  // bf16x2 pack of x1: [b][k2][q]
__device__ uint32_t g_x2b[(size_t)NPIX * 128];  // bf16x2 pack of x2: [b][k2][q]
__device__ uint32_t g_Wvb[128 * 256];    // bf16x2 (ln2_g-scaled W_val): [k2][n]
__device__ uint32_t g_Wob[128 * 256];    // bf16x2 W_out: [k2][m]
__device__ uint32_t g_Wqb[128 * 64];     // bf16x2 (ln1_g-scaled [W_off|W_att|0]): [k2][j]
__device__ uint32_t g_value[NPIX * Cc / 2];  // bf16x2: (B,Nq,C), pair (c, c+1)
__device__ uint2 g_pairs[(size_t)NPIX * 64]; // per (b,q,h): 16 x (byte offset, weight)
__device__ uint32_t g_S[NPIX * Cc / 2];      // bf16x2 sampled output (B,Nq,C)

// ---------------- helpers ----------------
__device__ __forceinline__ uint32_t packbf(float lo, float hi)
{
    __nv_bfloat162 h = __floats2bfloat162_rn(lo, hi);
    return *(uint32_t*)&h;
}

__device__ __forceinline__ void mma_bf16(float* d, const uint32_t* a, const uint32_t* b)
{
    asm volatile(
        "mma.sync.aligned.m16n8k16.row.col.f32.bf16.bf16.f32 "
        "{%0,%1,%2,%3}, {%4,%5,%6,%7}, {%8,%9}, {%0,%1,%2,%3};\n"
        : "+f"(d[0]), "+f"(d[1]), "+f"(d[2]), "+f"(d[3])
        : "r"(a[0]), "r"(a[1]), "r"(a[2]), "r"(a[3]), "r"(b[0]), "r"(b[1]));
}

__device__ __forceinline__ void cp16(void* smem_dst, const void* gmem_src)
{
    uint32_t sa = (uint32_t)__cvta_generic_to_shared(smem_dst);
    asm volatile("cp.async.cg.shared.global [%0], [%1], 16;\n" :: "r"(sa), "l"(gmem_src));
}
#define CP_COMMIT() asm volatile("cp.async.commit_group;\n" ::: "memory")
#define CP_WAIT1()  asm volatile("cp.async.wait_group 1;\n" ::: "memory")
#define CP_WAIT0()  asm volatile("cp.async.wait_group 0;\n" ::: "memory")

// ---------------- K_pre ----------------
// grid: 0 = const; 1..256 = stats+x-pack; 257..288 = qp GEMM (mma);
//       289..296 = Wval/Wout pack; 297 = Wq pack
__global__ void __launch_bounds__(256) k_pre(
    const float* __restrict__ x1, const float* __restrict__ x2,
    const float* __restrict__ ln1_g, const float* __restrict__ ln1_b,
    const float* __restrict__ ln2_g, const float* __restrict__ ln2_b,
    const float* __restrict__ pos_scale,
    const float* __restrict__ W_off, const float* __restrict__ b_off,
    const float* __restrict__ W_att, const float* __restrict__ b_att,
    const float* __restrict__ W_val, const float* __restrict__ b_val,
    const float* __restrict__ W_out)
{
    int bid = blockIdx.x;
    int tid = threadIdx.x;

    if (bid == 0) {
        float sG = 0.f, sc = 0.f;
        for (int k = 0; k < Cc; k++) {
            float w = W_val[k * Cc + tid];
            sG += ln2_g[k] * w;
            sc += ln2_b[k] * w;
        }
        g_vG[tid] = sG;
        g_vc[tid] = sc + b_val[tid];

        if (tid < 48) {
            float s1 = 0.f, s2 = 0.f, bb;
            if (tid < 32) {
                for (int k = 0; k < Cc; k++) {
                    float w = W_off[k * 32 + tid];
                    s1 += ln1_b[k] * w;
                    s2 += ln1_g[k] * w;
                }
                bb = b_off[tid];
            } else {
                int j = tid - 32;
                for (int k = 0; k < Cc; k++) {
                    float w = W_att[k * 16 + j];
                    s1 += ln1_b[k] * w;
                    s2 += ln1_g[k] * w;
                }
                bb = b_att[j];
            }
            g_c48[tid] = s1 + bb;
            g_gs48[tid] = s2;
        }
    } else if (bid <= 256) {
        // ---- per-pixel LN stats + bf16 pack ----
        int t = (bid - 1) * 256 + tid;          // 0 .. 2*NPIX-1
        int idx = t & (NPIX - 1);
        int b = idx >> 12, q = idx & (NQ - 1);
        const float* p = ((t < NPIX) ? x1 : x2) + b * (Cc * NQ) + q;
        uint32_t* xb = ((t < NPIX) ? g_x1b : g_x2b) + (size_t)(b * 128) * NQ + q;
        float s = 0.f, ss = 0.f;
#pragma unroll 8
        for (int k2 = 0; k2 < 128; k2++) {
            float v0 = p[(2 * k2) * NQ];
            float v1 = p[(2 * k2 + 1) * NQ];
            s += v0 + v1;
            ss += v0 * v0 + v1 * v1;
            xb[(size_t)k2 * NQ] = packbf(v0, v1);
        }
        float m = s * (1.0f / Cc);
        float var = ss * (1.0f / Cc) - m * m;
        float r = rsqrtf(var + EPSf);
        if (t < NPIX) { g_mean1[idx] = m; g_rstd1[idx] = r; }
        else          { g_mean2[idx] = m; g_rstd2[idx] = r; }
    } else if (bid <= 288) {
        // ---- qp GEMM: g_qp[q][j] = qpos[q][:] @ [W_off | W_att]  (raw W, no ln1_g) ----
        __shared__ float invf_s[128];
        __shared__ uint32_t Aq[16][136];
        __shared__ uint32_t Bq[16][72];

        int q0 = (bid - 257) * 128;
        float ps = pos_scale[0];
        if (tid < 128)
            invf_s[tid] = expf(-9.210340371976184f * (float)tid * (1.0f / 128.0f));
        __syncthreads();

        int wid = tid >> 5, lane = tid & 31;
        int warp_m = wid & 1, warp_n = wid >> 1;
        int lr = lane >> 2, lk = lane & 3;

        float acc[4][2][4];
#pragma unroll
        for (int i = 0; i < 4; i++)
#pragma unroll
            for (int j = 0; j < 2; j++)
#pragma unroll
                for (int r = 0; r < 4; r++) acc[i][j][r] = 0.f;

        for (int k0 = 0; k0 < Cc; k0 += 32) {
#pragma unroll
            for (int i = 0; i < 8; i++) {
                int lin = tid + i * 256;        // 2048 slots
                int k2 = lin >> 7;              // 0..15
                int q = lin & 127;
                int k = k0 + 2 * k2;
                float fq = (float)(q0 + q);
                float v0 = (k < 128) ? sinf(fq * invf_s[k]) : cosf(fq * invf_s[k - 128]);
                float v1 = (k + 1 < 128) ? sinf(fq * invf_s[k + 1]) : cosf(fq * invf_s[k - 127]);
                Aq[k2][q] = packbf(v0 * ps, v1 * ps);
            }
#pragma unroll
            for (int i = 0; i < 4; i++) {
                int lin = tid + i * 256;        // 1024 slots
                int j = lin & 63;
                int k2 = lin >> 6;
                int k = k0 + 2 * k2;
                float lo = 0.f, hi = 0.f;
                if (j < 32) {
                    lo = W_off[k * 32 + j];
                    hi = W_off[(k + 1) * 32 + j];
                } else if (j < 48) {
                    int jj = j - 32;
                    lo = W_att[k * 16 + jj];
                    hi = W_att[(k + 1) * 16 + jj];
                }
                Bq[k2][j] = packbf(lo, hi);
            }
            __syncthreads();
#pragma unroll
            for (int kk = 0; kk < 2; kk++) {
                int base = kk * 8;
                uint32_t a[4][4], bf[2][2];
#pragma unroll
                for (int mt = 0; mt < 4; mt++) {
                    int r = warp_m * 64 + mt * 16 + lr;
                    a[mt][0] = Aq[base + lk][r];
                    a[mt][1] = Aq[base + lk][r + 8];
                    a[mt][2] = Aq[base + lk + 4][r];
                    a[mt][3] = Aq[base + lk + 4][r + 8];
                }
#pragma unroll
                for (int nt = 0; nt < 2; nt++) {
                    int c = warp_n * 16 + nt * 8 + lr;
                    bf[nt][0] = Bq[base + lk][c];
                    bf[nt][1] = Bq[base + lk + 4][c];
                }
#pragma unroll
                for (int mt = 0; mt < 4; mt++)
#pragma unroll
                    for (int nt = 0; nt < 2; nt++)
                        mma_bf16(acc[mt][nt], a[mt], bf[nt]);
            }
            __syncthreads();
        }

        int lc2 = (lane & 3) * 2;
#pragma unroll
        for (int mt = 0; mt < 4; mt++) {
#pragma unroll
            for (int nt = 0; nt < 2; nt++) {
                int c = warp_n * 16 + nt * 8 + lc2;
                if (c < 48) {
                    int r1 = q0 + warp_m * 64 + mt * 16 + lr;
                    *(float2*)&g_qp[r1 * 48 + c] = make_float2(acc[mt][nt][0], acc[mt][nt][1]);
                    *(float2*)&g_qp[(r1 + 8) * 48 + c] = make_float2(acc[mt][nt][2], acc[mt][nt][3]);
                }
            }
        }
    } else if (bid <= 296) {
        int wb = bid - 289;                     // 0..7
        if (wb < 4) {
#pragma unroll 4
            for (int r = 0; r < 32; r++) {
                int k2 = wb * 32 + r;
                int k = 2 * k2;
                float g0 = ln2_g[k], g1 = ln2_g[k + 1];
                g_Wvb[k2 * 256 + tid] = packbf(W_val[k * 256 + tid] * g0,
                                               W_val[(k + 1) * 256 + tid] * g1);
            }
        } else {
#pragma unroll 4
            for (int r = 0; r < 32; r++) {
                int k2 = (wb - 4) * 32 + r;
                int k = 2 * k2;
                g_Wob[k2 * 256 + tid] = packbf(W_out[k * 256 + tid],
                                               W_out[(k + 1) * 256 + tid]);
            }
        }
    } else {
#pragma unroll 4
        for (int i = 0; i < 32; i++) {
            int lin = i * 256 + tid;            // 8192
            int k2 = lin >> 6, j = lin & 63;
            int k = 2 * k2;
            float lo = 0.f, hi = 0.f;
            if (j < 32) {
                lo = W_off[k * 32 + j] * ln1_g[k];
                hi = W_off[(k + 1) * 32 + j] * ln1_g[k + 1];
            } else if (j < 48) {
                int jj = j - 32;
                lo = W_att[k * 16 + jj] * ln1_g[k];
                hi = W_att[(k + 1) * 16 + jj] * ln1_g[k + 1];
            }
            g_Wqb[k2 * 64 + j] = packbf(lo, hi);
        }
    }
}

// ---------------- K_mid: merged value-GEMM (bids 0..511) + off/att GEMM (bids 512..767) ----------------
union SmemMid {
    struct { uint32_t A[2][16][136]; uint32_t B[2][16][136]; } val;
    struct {
        union {
            struct { uint32_t A[16][136]; uint32_t Bq[16][72]; } p1;
            float Out[128][52];
        } u;
    } off;
};

__global__ void __launch_bounds__(256, 2) k_mid()
{
    __shared__ SmemMid sm;
    int bid = blockIdx.x;
    int tid = threadIdx.x;
    int wid = tid >> 5, lane = tid & 31;
    int lr = lane >> 2, lk = lane & 3;

    if (bid < 512) {
        // ======== value GEMM (cp.async double-buffered) ========
        int v = bid;
        int b = v >> 6;
        int m0 = ((v >> 1) & 31) * 128;
        int n0 = (v & 1) * 128;
        int warp_m = wid & 1, warp_n = wid >> 1;

        float acc[4][4][4];
#pragma unroll
        for (int i = 0; i < 4; i++)
#pragma unroll
            for (int j = 0; j < 4; j++)
#pragma unroll
                for (int r = 0; r < 4; r++) acc[i][j][r] = 0.f;

        const uint32_t* Ab = g_x2b + (size_t)(b * 128) * NQ + m0;

        int row0 = tid >> 5, seg0 = tid & 31;
        int row1 = (tid + 256) >> 5, seg1 = (tid + 256) & 31;

        cp16(&sm.val.A[0][row0][seg0 * 4], Ab + (size_t)row0 * NQ + seg0 * 4);
        cp16(&sm.val.A[0][row1][seg1 * 4], Ab + (size_t)row1 * NQ + seg1 * 4);
        cp16(&sm.val.B[0][row0][seg0 * 4], g_Wvb + row0 * 256 + n0 + seg0 * 4);
        cp16(&sm.val.B[0][row1][seg1 * 4], g_Wvb + row1 * 256 + n0 + seg1 * 4);
        CP_COMMIT();

        for (int it = 0; it < 8; it++) {
            if (it < 7) {
                int k2b = (it + 1) * 16;
                int s = (it + 1) & 1;
                cp16(&sm.val.A[s][row0][seg0 * 4], Ab + (size_t)(k2b + row0) * NQ + seg0 * 4);
                cp16(&sm.val.A[s][row1][seg1 * 4], Ab + (size_t)(k2b + row1) * NQ + seg1 * 4);
                cp16(&sm.val.B[s][row0][seg0 * 4], g_Wvb + (k2b + row0) * 256 + n0 + seg0 * 4);
                cp16(&sm.val.B[s][row1][seg1 * 4], g_Wvb + (k2b + row1) * 256 + n0 + seg1 * 4);
                CP_COMMIT();
                CP_WAIT1();
            } else {
                CP_WAIT0();
            }
            __syncthreads();
            int s = it & 1;
#pragma unroll
            for (int kk = 0; kk < 2; kk++) {
                int base = kk * 8;
                uint32_t a[4][4], bf[4][2];
#pragma unroll
                for (int mt = 0; mt < 4; mt++) {
                    int r = warp_m * 64 + mt * 16 + lr;
                    a[mt][0] = sm.val.A[s][base + lk][r];
                    a[mt][1] = sm.val.A[s][base + lk][r + 8];
                    a[mt][2] = sm.val.A[s][base + lk + 4][r];
                    a[mt][3] = sm.val.A[s][base + lk + 4][r + 8];
                }
#pragma unroll
                for (int nt = 0; nt < 4; nt++) {
                    int c = warp_n * 32 + nt * 8 + lr;
                    bf[nt][0] = sm.val.B[s][base + lk][c];
                    bf[nt][1] = sm.val.B[s][base + lk + 4][c];
                }
#pragma unroll
                for (int mt = 0; mt < 4; mt++)
#pragma unroll
                    for (int nt = 0; nt < 4; nt++)
                        mma_bf16(acc[mt][nt], a[mt], bf[nt]);
            }
            __syncthreads();
        }

        int lc2 = (lane & 3) * 2;
#pragma unroll
        for (int mt = 0; mt < 4; mt++) {
            int q1 = m0 + warp_m * 64 + mt * 16 + lr;
            int q2 = q1 + 8;
            int g1 = b * NQ + q1, g2 = b * NQ + q2;
            float r1 = g_rstd2[g1], mm1 = r1 * g_mean2[g1];
            float r2 = g_rstd2[g2], mm2 = r2 * g_mean2[g2];
#pragma unroll
            for (int nt = 0; nt < 4; nt++) {
                int c = n0 + warp_n * 32 + nt * 8 + lc2;
                float vG0 = g_vG[c], vG1 = g_vG[c + 1];
                float vc0 = g_vc[c], vc1 = g_vc[c + 1];
                g_value[(size_t)g1 * 128 + (c >> 1)] =
                    packbf(r1 * acc[mt][nt][0] - mm1 * vG0 + vc0,
                           r1 * acc[mt][nt][1] - mm1 * vG1 + vc1);
                g_value[(size_t)g2 * 128 + (c >> 1)] =
                    packbf(r2 * acc[mt][nt][2] - mm2 * vG0 + vc0,
                           r2 * acc[mt][nt][3] - mm2 * vG1 + vc1);
            }
        }
    } else {
        // ======== off/att GEMM + softmax + pair precompute ========
        int o = bid - 512;
        int b = o >> 5;
        int q0 = (o & 31) * 128;
        int warp_m = wid & 1, warp_n = wid >> 1;

        float acc[4][2][4];
#pragma unroll
        for (int i = 0; i < 4; i++)
#pragma unroll
            for (int j = 0; j < 2; j++)
#pragma unroll
                for (int r = 0; r < 4; r++) acc[i][j][r] = 0.f;

        const uint32_t* Ab = g_x1b + (size_t)(b * 128) * NQ + q0;

        for (int k0 = 0; k0 < Cc; k0 += 32) {
            int k2b = k0 >> 1;
#pragma unroll
            for (int i = 0; i < 2; i++) {
                int lin = tid + i * 256;
                int row = lin >> 5, seg = lin & 31;
                *(uint4*)&sm.off.u.p1.A[row][seg * 4] =
                    *(const uint4*)(Ab + (size_t)(k2b + row) * NQ + seg * 4);
            }
            {
                int row = tid >> 4, seg = tid & 15;
                *(uint4*)&sm.off.u.p1.Bq[row][seg * 4] =
                    *(const uint4*)(g_Wqb + (k2b + row) * 64 + seg * 4);
            }
            __syncthreads();
#pragma unroll
            for (int kk = 0; kk < 2; kk++) {
                int base = kk * 8;
                uint32_t a[4][4], bf[2][2];
#pragma unroll
                for (int mt = 0; mt < 4; mt++) {
                    int r = warp_m * 64 + mt * 16 + lr;
                    a[mt][0] = sm.off.u.p1.A[base + lk][r];
                    a[mt][1] = sm.off.u.p1.A[base + lk][r + 8];
                    a[mt][2] = sm.off.u.p1.A[base + lk + 4][r];
                    a[mt][3] = sm.off.u.p1.A[base + lk + 4][r + 8];
                }
#pragma unroll
                for (int nt = 0; nt < 2; nt++) {
                    int c = warp_n * 16 + nt * 8 + lr;
                    bf[nt][0] = sm.off.u.p1.Bq[base + lk][c];
                    bf[nt][1] = sm.off.u.p1.Bq[base + lk + 4][c];
                }
#pragma unroll
                for (int mt = 0; mt < 4; mt++)
#pragma unroll
                    for (int nt = 0; nt < 2; nt++)
                        mma_bf16(acc[mt][nt], a[mt], bf[nt]);
            }
            __syncthreads();
        }

        int lc2 = (lane & 3) * 2;
#pragma unroll
        for (int mt = 0; mt < 4; mt++) {
#pragma unroll
            for (int nt = 0; nt < 2; nt++) {
                int c = warp_n * 16 + nt * 8 + lc2;
                if (c < 48) {
                    int r = warp_m * 64 + mt * 16 + lr;
                    *(float2*)&sm.off.u.Out[r][c]     = make_float2(acc[mt][nt][0], acc[mt][nt][1]);
                    *(float2*)&sm.off.u.Out[r + 8][c] = make_float2(acc[mt][nt][2], acc[mt][nt][3]);
                }
            }
        }
        __syncthreads();

        if (tid < 128) {
            int qg = q0 + tid;
            int gidx = b * NQ + qg;
            float r = g_rstd1[gidx];
            float mterm = r * g_mean1[gidx];
            float vals[48];
#pragma unroll
            for (int j = 0; j < 48; j++)
                vals[j] = r * sm.off.u.Out[tid][j] - mterm * g_gs48[j] + g_c48[j] + g_qp[qg * 48 + j];

            float wpix = (float)(qg & 63);
            float hpix = (float)(qg >> 6);
#pragma unroll
            for (int h = 0; h < NHh; h++) {
                float* av = &vals[32 + h * 4];
                float mx = fmaxf(fmaxf(av[0], av[1]), fmaxf(av[2], av[3]));
                float e0 = __expf(av[0] - mx), e1 = __expf(av[1] - mx);
                float e2 = __expf(av[2] - mx), e3 = __expf(av[3] - mx);
                float inv = 1.0f / (e0 + e1 + e2 + e3);
                float aw[4] = {e0 * inv, e1 * inv, e2 * inv, e3 * inv};

                uint2* pp = g_pairs + ((size_t)gidx * 4 + h) * 16;
#pragma unroll
                for (int p = 0; p < NPp; p++) {
                    float px = wpix + vals[h * 8 + p * 2];
                    float py = hpix + vals[h * 8 + p * 2 + 1];
                    float fx = floorf(px), fy = floorf(py);
                    int ix = (int)fx, iy = (int)fy;
                    float wx = px - fx, wy = py - fy;
                    float a = aw[p];
                    uint4 st0, st1;
#pragma unroll
                    for (int c = 0; c < 4; c++) {
                        int cx = ix + (c & 1);
                        int cy = iy + (c >> 1);
                        bool valid = (cx >= 0) & (cx < Ww) & (cy >= 0) & (cy < Hh);
                        float wgt = valid ? ((c & 1) ? wx : 1.f - wx) * ((c >> 1) ? wy : 1.f - wy) * a : 0.f;
                        uint32_t off = valid ? (uint32_t)(cy * Ww + cx) * 512u : 0u;
                        if (c == 0) { st0.x = off; st0.y = __float_as_uint(wgt); }
                        if (c == 1) { st0.z = off; st0.w = __float_as_uint(wgt); }
                        if (c == 2) { st1.x = off; st1.y = __float_as_uint(wgt); }
                        if (c == 3) { st1.z = off; st1.w = __float_as_uint(wgt); }
                    }
                    *(uint4*)&pp[p * 4]     = st0;
                    *(uint4*)&pp[p * 4 + 2] = st1;
                }
            }
        }
    }
}

// ---------------- K5: bilinear sampling — warp = (q, 4 heads), lane = 8 channels ----------------
__global__ void __launch_bounds__(512) k_sample()
{
    int tid = threadIdx.x;
    int warp = tid >> 5, lane = tid & 31;
    int b = blockIdx.y;
    int qg = blockIdx.x * 16 + warp;
    int head = lane >> 3;
    int grp = lane & 7;
    int gidx = b * NQ + qg;

    uint4 pr = *((const uint4*)(g_pairs + ((size_t)gidx * 4 + head) * 16) + grp);

    const char* __restrict__ vbase =
        (const char*)g_value + (size_t)b * NQ * 512 + head * 128 + grp * 16;

    float a0 = 0.f, a1 = 0.f, a2 = 0.f, a3 = 0.f;
    float a4 = 0.f, a5 = 0.f, a6 = 0.f, a7 = 0.f;
#pragma unroll
    for (int c = 0; c < 16; c++) {
        int srcl = c >> 1;
        uint32_t ob = __shfl_sync(0xFFFFFFFFu, (c & 1) ? pr.z : pr.x, srcl, 8);
        float w = __uint_as_float(__shfl_sync(0xFFFFFFFFu, (c & 1) ? pr.w : pr.y, srcl, 8));
        uint4 v = *(const uint4*)(vbase + ob);
        a0 += w * __uint_as_float(v.x << 16);
        a1 += w * __uint_as_float(v.x & 0xFFFF0000u);
        a2 += w * __uint_as_float(v.y << 16);
        a3 += w * __uint_as_float(v.y & 0xFFFF0000u);
        a4 += w * __uint_as_float(v.z << 16);
        a5 += w * __uint_as_float(v.z & 0xFFFF0000u);
        a6 += w * __uint_as_float(v.w << 16);
        a7 += w * __uint_as_float(v.w & 0xFFFF0000u);
    }
    uint4 st;
    st.x = packbf(a0, a1);
    st.y = packbf(a2, a3);
    st.z = packbf(a4, a5);
    st.w = packbf(a6, a7);
    *(uint4*)((char*)g_S + (size_t)gidx * 512 + head * 128 + grp * 16) = st;
}

// ---------------- K6: output GEMM, CTA 128(m) x 256(q), warp 64x64 ----------------
__global__ void __launch_bounds__(256, 1) k_gemm_out(const float* __restrict__ x2,
                                                     const float* __restrict__ b_out,
                                                     float* __restrict__ out)
{
    __shared__ uint32_t As2[2][16][136];
    __shared__ uint32_t Bs2[2][16][264];

    int b = blockIdx.z;
    int m0 = blockIdx.x * 128;      // c' half
    int n0 = blockIdx.y * 256;      // q tile
    int tid = threadIdx.x;
    int wid = tid >> 5, lane = tid & 31;
    int warp_m = wid & 1, warp_n = wid >> 1;   // warp tile 64(m) x 64(q)
    int lr = lane >> 2, lk = lane & 3;

    float acc[4][8][4];
#pragma unroll
    for (int i = 0; i < 4; i++)
#pragma unroll
        for (int j = 0; j < 8; j++)
#pragma unroll
            for (int r = 0; r < 4; r++) acc[i][j][r] = 0.f;

    const uint32_t* Sb = g_S + (size_t)(b * NQ + n0) * 128;

    int row0 = tid >> 5, seg0 = tid & 31;       // A: 512 uint4 over 2 iters
    int row1 = (tid + 256) >> 5, seg1 = (tid + 256) & 31;

    // B: one q-row per thread, 16 k2 per stage = 4 uint4 loads
    uint4 breg[4];

    // prologue tile 0
    cp16(&As2[0][row0][seg0 * 4], g_Wob + row0 * 256 + m0 + seg0 * 4);
    cp16(&As2[0][row1][seg1 * 4], g_Wob + row1 * 256 + m0 + seg1 * 4);
    CP_COMMIT();
#pragma unroll
    for (int i = 0; i < 4; i++)
        breg[i] = *(const uint4*)(Sb + (size_t)tid * 128 + i * 4);
#pragma unroll
    for (int i = 0; i < 4; i++) {
        Bs2[0][i * 4 + 0][tid] = breg[i].x;
        Bs2[0][i * 4 + 1][tid] = breg[i].y;
        Bs2[0][i * 4 + 2][tid] = breg[i].z;
        Bs2[0][i * 4 + 3][tid] = breg[i].w;
    }

    for (int it = 0; it < 8; it++) {
        if (it < 7) {
            int k2b = (it + 1) * 16;
            int s = (it + 1) & 1;
            cp16(&As2[s][row0][seg0 * 4], g_Wob + (k2b + row0) * 256 + m0 + seg0 * 4);
            cp16(&As2[s][row1][seg1 * 4], g_Wob + (k2b + row1) * 256 + m0 + seg1 * 4);
            CP_COMMIT();
#pragma unroll
            for (int i = 0; i < 4; i++)
                breg[i] = *(const uint4*)(Sb + (size_t)tid * 128 + k2b + i * 4);
            CP_WAIT1();
        } else {
            CP_WAIT0();
        }
        __syncthreads();
        int s = it & 1;
#pragma unroll
        for (int kk = 0; kk < 2; kk++) {
            int base = kk * 8;
            uint32_t a[4][4], bf[8][2];
#pragma unroll
            for (int mt = 0; mt < 4; mt++) {
                int r = warp_m * 64 + mt * 16 + lr;
                a[mt][0] = As2[s][base + lk][r];
                a[mt][1] = As2[s][base + lk][r + 8];
                a[mt][2] = As2[s][base + lk + 4][r];
                a[mt][3] = As2[s][base + lk + 4][r + 8];
            }
#pragma unroll
            for (int nt = 0; nt < 8; nt++) {
                int c = warp_n * 64 + nt * 8 + lr;
                bf[nt][0] = Bs2[s][base + lk][c];
                bf[nt][1] = Bs2[s][base + lk + 4][c];
            }
#pragma unroll
            for (int mt = 0; mt < 4; mt++)
#pragma unroll
                for (int nt = 0; nt < 8; nt++)
                    mma_bf16(acc[mt][nt], a[mt], bf[nt]);
        }
        if (it < 7) {
            int s2 = (it + 1) & 1;
#pragma unroll
            for (int i = 0; i < 4; i++) {
                Bs2[s2][i * 4 + 0][tid] = breg[i].x;
                Bs2[s2][i * 4 + 1][tid] = breg[i].y;
                Bs2[s2][i * 4 + 2][tid] = breg[i].z;
                Bs2[s2][i * 4 + 3][tid] = breg[i].w;
            }
        }
        __syncthreads();
    }

    // epilogue: + b_out + x2 residual (fp32 out, (B,C,H,W))
    int lc2 = (lane & 3) * 2;
#pragma unroll
    for (int mt = 0; mt < 4; mt++) {
        int c1 = m0 + warp_m * 64 + mt * 16 + lr;
        int c2 = c1 + 8;
        float bo1 = b_out[c1], bo2 = b_out[c2];
        size_t base1 = ((size_t)b * Cc + c1) * NQ;
        size_t base2 = ((size_t)b * Cc + c2) * NQ;
#pragma unroll
        for (int nt = 0; nt < 8; nt++) {
            int q = n0 + warp_n * 64 + nt * 8 + lc2;
            float2 x1v = *(const float2*)(x2 + base1 + q);
            float2 x2v = *(const float2*)(x2 + base2 + q);
            float2 o1, o2;
            o1.x = acc[mt][nt][0] + bo1 + x1v.x;
            o1.y = acc[mt][nt][1] + bo1 + x1v.y;
            o2.x = acc[mt][nt][2] + bo2 + x2v.x;
            o2.y = acc[mt][nt][3] + bo2 + x2v.y;
            *(float2*)(out + base1 + q) = o1;
            *(float2*)(out + base2 + q) = o2;
        }
    }
}

// ---------------- launch ----------------
extern "C" void kernel_launch(void* const* d_in, const int* in_sizes, int n_in,
                              void* d_out, int out_size)
{
    const float* x1        = (const float*)d_in[0];
    const float* x2        = (const float*)d_in[1];
    const float* ln1_g     = (const float*)d_in[2];
    const float* ln1_b     = (const float*)d_in[3];
    const float* ln2_g     = (const float*)d_in[4];
    const float* ln2_b     = (const float*)d_in[5];
    const float* pos_scale = (const float*)d_in[6];
    const float* W_off     = (const float*)d_in[7];
    const float* b_off     = (const float*)d_in[8];
    const float* W_att     = (const float*)d_in[9];
    const float* b_att     = (const float*)d_in[10];
    const float* W_val     = (const float*)d_in[11];
    const float* b_val     = (const float*)d_in[12];
    const float* W_out     = (const float*)d_in[13];
    const float* b_out     = (const float*)d_in[14];
    float* out = (float*)d_out;

    k_pre<<<298, 256>>>(x1, x2, ln1_g, ln1_b, ln2_g, ln2_b, pos_scale,
                        W_off, b_off, W_att, b_att, W_val, b_val, W_out);
    k_mid<<<768, 256>>>();
    k_sample<<<dim3(NQ / 16, Bb), 512>>>();
    k_gemm_out<<<dim3(2, NQ / 256, Bb), 256>>>(x2, b_out, out);
}

// round 13
// speedup vs baseline: 1.0521x; 1.0521x over previous
#include <cuda_runtime.h>
#include <cuda_bf16.h>
#include <math.h>
#include <stdint.h>

// Problem constants
#define Bb   8
#define Cc   256
#define Hh   64
#define Ww   64
#define NQ   4096           // H*W
#define NPIX (Bb*NQ)        // 32768
#define NHh  4
#define NPp  4
#define Dd   64
#define EPSf 1e-5f

// ---------------- scratch (static device globals; no allocation) ----------------
__device__ float g_mean1[NPIX], g_rstd1[NPIX], g_mean2[NPIX], g_rstd2[NPIX];
__device__ float g_qp[NQ * 48];
__device__ float g_c48[48];
__device__ float g_gs48[48];
__device__ float g_vG[Cc];
__device__ float g_vc[Cc];
__device__ uint32_t g_x1b[(size_t)NPIX * 128];
__device__ uint32_t g_x2b[(size_t)NPIX * 128];
__device__ uint32_t g_Wvb[128 * 256];
__device__ uint32_t g_Wob[128 * 256];
__device__ uint32_t g_Wqb[128 * 64];
__device__ uint32_t g_value[NPIX * Cc / 2];
__device__ uint2 g_pairs[(size_t)NPIX * 64];
__device__ uint32_t g_S[NPIX * Cc / 2];

// ---------------- helpers ----------------
__device__ __forceinline__ uint32_t packbf(float lo, float hi)
{
    __nv_bfloat162 h = __floats2bfloat162_rn(lo, hi);
    return *(uint32_t*)&h;
}

__device__ __forceinline__ void mma_bf16(float* d, const uint32_t* a, const uint32_t* b)
{
    asm volatile(
        "mma.sync.aligned.m16n8k16.row.col.f32.bf16.bf16.f32 "
        "{%0,%1,%2,%3}, {%4,%5,%6,%7}, {%8,%9}, {%0,%1,%2,%3};\n"
        : "+f"(d[0]), "+f"(d[1]), "+f"(d[2]), "+f"(d[3])
        : "r"(a[0]), "r"(a[1]), "r"(a[2]), "r"(a[3]), "r"(b[0]), "r"(b[1]));
}

__device__ __forceinline__ void cp16(void* smem_dst, const void* gmem_src)
{
    uint32_t sa = (uint32_t)__cvta_generic_to_shared(smem_dst);
    asm volatile("cp.async.cg.shared.global [%0], [%1], 16;\n" :: "r"(sa), "l"(gmem_src));
}
#define CP_COMMIT() asm volatile("cp.async.commit_group;\n" ::: "memory")
#define CP_WAIT1()  asm volatile("cp.async.wait_group 1;\n" ::: "memory")
#define CP_WAIT0()  asm volatile("cp.async.wait_group 0;\n" ::: "memory")

#define PDL_TRIGGER() asm volatile("griddepcontrol.launch_dependents;" ::: "memory")
#define PDL_WAIT()    asm volatile("griddepcontrol.wait;" ::: "memory")

// ---------------- K_pre ----------------
// grid: 0 = const; 1..256 = stats+x-pack; 257..288 = qp GEMM (mma);
//       289..296 = Wval/Wout pack; 297 = Wq pack
__global__ void __launch_bounds__(256) k_pre(
    const float* __restrict__ x1, const float* __restrict__ x2,
    const float* __restrict__ ln1_g, const float* __restrict__ ln1_b,
    const float* __restrict__ ln2_g, const float* __restrict__ ln2_b,
    const float* __restrict__ pos_scale,
    const float* __restrict__ W_off, const float* __restrict__ b_off,
    const float* __restrict__ W_att, const float* __restrict__ b_att,
    const float* __restrict__ W_val, const float* __restrict__ b_val,
    const float* __restrict__ W_out)
{
    int bid = blockIdx.x;
    int tid = threadIdx.x;

    if (bid == 0) {
        float sG = 0.f, sc = 0.f;
        for (int k = 0; k < Cc; k++) {
            float w = W_val[k * Cc + tid];
            sG += ln2_g[k] * w;
            sc += ln2_b[k] * w;
        }
        g_vG[tid] = sG;
        g_vc[tid] = sc + b_val[tid];

        if (tid < 48) {
            float s1 = 0.f, s2 = 0.f, bb;
            if (tid < 32) {
                for (int k = 0; k < Cc; k++) {
                    float w = W_off[k * 32 + tid];
                    s1 += ln1_b[k] * w;
                    s2 += ln1_g[k] * w;
                }
                bb = b_off[tid];
            } else {
                int j = tid - 32;
                for (int k = 0; k < Cc; k++) {
                    float w = W_att[k * 16 + j];
                    s1 += ln1_b[k] * w;
                    s2 += ln1_g[k] * w;
                }
                bb = b_att[j];
            }
            g_c48[tid] = s1 + bb;
            g_gs48[tid] = s2;
        }
    } else if (bid <= 256) {
        int t = (bid - 1) * 256 + tid;
        int idx = t & (NPIX - 1);
        int b = idx >> 12, q = idx & (NQ - 1);
        const float* p = ((t < NPIX) ? x1 : x2) + b * (Cc * NQ) + q;
        uint32_t* xb = ((t < NPIX) ? g_x1b : g_x2b) + (size_t)(b * 128) * NQ + q;
        float s = 0.f, ss = 0.f;
#pragma unroll 8
        for (int k2 = 0; k2 < 128; k2++) {
            float v0 = p[(2 * k2) * NQ];
            float v1 = p[(2 * k2 + 1) * NQ];
            s += v0 + v1;
            ss += v0 * v0 + v1 * v1;
            xb[(size_t)k2 * NQ] = packbf(v0, v1);
        }
        float m = s * (1.0f / Cc);
        float var = ss * (1.0f / Cc) - m * m;
        float r = rsqrtf(var + EPSf);
        if (t < NPIX) { g_mean1[idx] = m; g_rstd1[idx] = r; }
        else          { g_mean2[idx] = m; g_rstd2[idx] = r; }
    } else if (bid <= 288) {
        __shared__ float invf_s[128];
        __shared__ uint32_t Aq[16][136];
        __shared__ uint32_t Bq[16][72];

        int q0 = (bid - 257) * 128;
        float ps = pos_scale[0];
        if (tid < 128)
            invf_s[tid] = expf(-9.210340371976184f * (float)tid * (1.0f / 128.0f));
        __syncthreads();

        int wid = tid >> 5, lane = tid & 31;
        int warp_m = wid & 1, warp_n = wid >> 1;
        int lr = lane >> 2, lk = lane & 3;

        float acc[4][2][4];
#pragma unroll
        for (int i = 0; i < 4; i++)
#pragma unroll
            for (int j = 0; j < 2; j++)
#pragma unroll
                for (int r = 0; r < 4; r++) acc[i][j][r] = 0.f;

        for (int k0 = 0; k0 < Cc; k0 += 32) {
#pragma unroll
            for (int i = 0; i < 8; i++) {
                int lin = tid + i * 256;
                int k2 = lin >> 7;
                int q = lin & 127;
                int k = k0 + 2 * k2;
                float fq = (float)(q0 + q);
                float v0 = (k < 128) ? sinf(fq * invf_s[k]) : cosf(fq * invf_s[k - 128]);
                float v1 = (k + 1 < 128) ? sinf(fq * invf_s[k + 1]) : cosf(fq * invf_s[k - 127]);
                Aq[k2][q] = packbf(v0 * ps, v1 * ps);
            }
#pragma unroll
            for (int i = 0; i < 4; i++) {
                int lin = tid + i * 256;
                int j = lin & 63;
                int k2 = lin >> 6;
                int k = k0 + 2 * k2;
                float lo = 0.f, hi = 0.f;
                if (j < 32) {
                    lo = W_off[k * 32 + j];
                    hi = W_off[(k + 1) * 32 + j];
                } else if (j < 48) {
                    int jj = j - 32;
                    lo = W_att[k * 16 + jj];
                    hi = W_att[(k + 1) * 16 + jj];
                }
                Bq[k2][j] = packbf(lo, hi);
            }
            __syncthreads();
#pragma unroll
            for (int kk = 0; kk < 2; kk++) {
                int base = kk * 8;
                uint32_t a[4][4], bf[2][2];
#pragma unroll
                for (int mt = 0; mt < 4; mt++) {
                    int r = warp_m * 64 + mt * 16 + lr;
                    a[mt][0] = Aq[base + lk][r];
                    a[mt][1] = Aq[base + lk][r + 8];
                    a[mt][2] = Aq[base + lk + 4][r];
                    a[mt][3] = Aq[base + lk + 4][r + 8];
                }
#pragma unroll
                for (int nt = 0; nt < 2; nt++) {
                    int c = warp_n * 16 + nt * 8 + lr;
                    bf[nt][0] = Bq[base + lk][c];
                    bf[nt][1] = Bq[base + lk + 4][c];
                }
#pragma unroll
                for (int mt = 0; mt < 4; mt++)
#pragma unroll
                    for (int nt = 0; nt < 2; nt++)
                        mma_bf16(acc[mt][nt], a[mt], bf[nt]);
            }
            __syncthreads();
        }

        int lc2 = (lane & 3) * 2;
#pragma unroll
        for (int mt = 0; mt < 4; mt++) {
#pragma unroll
            for (int nt = 0; nt < 2; nt++) {
                int c = warp_n * 16 + nt * 8 + lc2;
                if (c < 48) {
                    int r1 = q0 + warp_m * 64 + mt * 16 + lr;
                    *(float2*)&g_qp[r1 * 48 + c] = make_float2(acc[mt][nt][0], acc[mt][nt][1]);
                    *(float2*)&g_qp[(r1 + 8) * 48 + c] = make_float2(acc[mt][nt][2], acc[mt][nt][3]);
                }
            }
        }
    } else if (bid <= 296) {
        int wb = bid - 289;
        if (wb < 4) {
#pragma unroll 4
            for (int r = 0; r < 32; r++) {
                int k2 = wb * 32 + r;
                int k = 2 * k2;
                float g0 = ln2_g[k], g1 = ln2_g[k + 1];
                g_Wvb[k2 * 256 + tid] = packbf(W_val[k * 256 + tid] * g0,
                                               W_val[(k + 1) * 256 + tid] * g1);
            }
        } else {
#pragma unroll 4
            for (int r = 0; r < 32; r++) {
                int k2 = (wb - 4) * 32 + r;
                int k = 2 * k2;
                g_Wob[k2 * 256 + tid] = packbf(W_out[k * 256 + tid],
                                               W_out[(k + 1) * 256 + tid]);
            }
        }
    } else {
#pragma unroll 4
        for (int i = 0; i < 32; i++) {
            int lin = i * 256 + tid;
            int k2 = lin >> 6, j = lin & 63;
            int k = 2 * k2;
            float lo = 0.f, hi = 0.f;
            if (j < 32) {
                lo = W_off[k * 32 + j] * ln1_g[k];
                hi = W_off[(k + 1) * 32 + j] * ln1_g[k + 1];
            } else if (j < 48) {
                int jj = j - 32;
                lo = W_att[k * 16 + jj] * ln1_g[k];
                hi = W_att[(k + 1) * 16 + jj] * ln1_g[k + 1];
            }
            g_Wqb[k2 * 64 + j] = packbf(lo, hi);
        }
    }
    PDL_TRIGGER();
}

// ---------------- K_mid: merged value-GEMM (bids 0..511) + off/att GEMM (bids 512..767) ----------------
union SmemMid {
    struct { uint32_t A[2][16][136]; uint32_t B[2][16][136]; } val;
    struct {
        union {
            struct { uint32_t A[16][136]; uint32_t Bq[16][72]; } p1;
            float Out[128][52];
        } u;
    } off;
};

__global__ void __launch_bounds__(256, 2) k_mid()
{
    __shared__ SmemMid sm;
    int bid = blockIdx.x;
    int tid = threadIdx.x;
    int wid = tid >> 5, lane = tid & 31;
    int lr = lane >> 2, lk = lane & 3;

    PDL_WAIT();

    if (bid < 512) {
        int v = bid;
        int b = v >> 6;
        int m0 = ((v >> 1) & 31) * 128;
        int n0 = (v & 1) * 128;
        int warp_m = wid & 1, warp_n = wid >> 1;

        float acc[4][4][4];
#pragma unroll
        for (int i = 0; i < 4; i++)
#pragma unroll
            for (int j = 0; j < 4; j++)
#pragma unroll
                for (int r = 0; r < 4; r++) acc[i][j][r] = 0.f;

        const uint32_t* Ab = g_x2b + (size_t)(b * 128) * NQ + m0;

        int row0 = tid >> 5, seg0 = tid & 31;
        int row1 = (tid + 256) >> 5, seg1 = (tid + 256) & 31;

        cp16(&sm.val.A[0][row0][seg0 * 4], Ab + (size_t)row0 * NQ + seg0 * 4);
        cp16(&sm.val.A[0][row1][seg1 * 4], Ab + (size_t)row1 * NQ + seg1 * 4);
        cp16(&sm.val.B[0][row0][seg0 * 4], g_Wvb + row0 * 256 + n0 + seg0 * 4);
        cp16(&sm.val.B[0][row1][seg1 * 4], g_Wvb + row1 * 256 + n0 + seg1 * 4);
        CP_COMMIT();

        for (int it = 0; it < 8; it++) {
            if (it < 7) {
                int k2b = (it + 1) * 16;
                int s = (it + 1) & 1;
                cp16(&sm.val.A[s][row0][seg0 * 4], Ab + (size_t)(k2b + row0) * NQ + seg0 * 4);
                cp16(&sm.val.A[s][row1][seg1 * 4], Ab + (size_t)(k2b + row1) * NQ + seg1 * 4);
                cp16(&sm.val.B[s][row0][seg0 * 4], g_Wvb + (k2b + row0) * 256 + n0 + seg0 * 4);
                cp16(&sm.val.B[s][row1][seg1 * 4], g_Wvb + (k2b + row1) * 256 + n0 + seg1 * 4);
                CP_COMMIT();
                CP_WAIT1();
            } else {
                CP_WAIT0();
            }
            __syncthreads();
            int s = it & 1;
#pragma unroll
            for (int kk = 0; kk < 2; kk++) {
                int base = kk * 8;
                uint32_t a[4][4], bf[4][2];
#pragma unroll
                for (int mt = 0; mt < 4; mt++) {
                    int r = warp_m * 64 + mt * 16 + lr;
                    a[mt][0] = sm.val.A[s][base + lk][r];
                    a[mt][1] = sm.val.A[s][base + lk][r + 8];
                    a[mt][2] = sm.val.A[s][base + lk + 4][r];
                    a[mt][3] = sm.val.A[s][base + lk + 4][r + 8];
                }
#pragma unroll
                for (int nt = 0; nt < 4; nt++) {
                    int c = warp_n * 32 + nt * 8 + lr;
                    bf[nt][0] = sm.val.B[s][base + lk][c];
                    bf[nt][1] = sm.val.B[s][base + lk + 4][c];
                }
#pragma unroll
                for (int mt = 0; mt < 4; mt++)
#pragma unroll
                    for (int nt = 0; nt < 4; nt++)
                        mma_bf16(acc[mt][nt], a[mt], bf[nt]);
            }
            __syncthreads();
        }

        int lc2 = (lane & 3) * 2;
#pragma unroll
        for (int mt = 0; mt < 4; mt++) {
            int q1 = m0 + warp_m * 64 + mt * 16 + lr;
            int q2 = q1 + 8;
            int g1 = b * NQ + q1, g2 = b * NQ + q2;
            float r1 = g_rstd2[g1], mm1 = r1 * g_mean2[g1];
            float r2 = g_rstd2[g2], mm2 = r2 * g_mean2[g2];
#pragma unroll
            for (int nt = 0; nt < 4; nt++) {
                int c = n0 + warp_n * 32 + nt * 8 + lc2;
                float vG0 = g_vG[c], vG1 = g_vG[c + 1];
                float vc0 = g_vc[c], vc1 = g_vc[c + 1];
                g_value[(size_t)g1 * 128 + (c >> 1)] =
                    packbf(r1 * acc[mt][nt][0] - mm1 * vG0 + vc0,
                           r1 * acc[mt][nt][1] - mm1 * vG1 + vc1);
                g_value[(size_t)g2 * 128 + (c >> 1)] =
                    packbf(r2 * acc[mt][nt][2] - mm2 * vG0 + vc0,
                           r2 * acc[mt][nt][3] - mm2 * vG1 + vc1);
            }
        }
    } else {
        int o = bid - 512;
        int b = o >> 5;
        int q0 = (o & 31) * 128;
        int warp_m = wid & 1, warp_n = wid >> 1;

        float acc[4][2][4];
#pragma unroll
        for (int i = 0; i < 4; i++)
#pragma unroll
            for (int j = 0; j < 2; j++)
#pragma unroll
                for (int r = 0; r < 4; r++) acc[i][j][r] = 0.f;

        const uint32_t* Ab = g_x1b + (size_t)(b * 128) * NQ + q0;

        for (int k0 = 0; k0 < Cc; k0 += 32) {
            int k2b = k0 >> 1;
#pragma unroll
            for (int i = 0; i < 2; i++) {
                int lin = tid + i * 256;
                int row = lin >> 5, seg = lin & 31;
                *(uint4*)&sm.off.u.p1.A[row][seg * 4] =
                    *(const uint4*)(Ab + (size_t)(k2b + row) * NQ + seg * 4);
            }
            {
                int row = tid >> 4, seg = tid & 15;
                *(uint4*)&sm.off.u.p1.Bq[row][seg * 4] =
                    *(const uint4*)(g_Wqb + (k2b + row) * 64 + seg * 4);
            }
            __syncthreads();
#pragma unroll
            for (int kk = 0; kk < 2; kk++) {
                int base = kk * 8;
                uint32_t a[4][4], bf[2][2];
#pragma unroll
                for (int mt = 0; mt < 4; mt++) {
                    int r = warp_m * 64 + mt * 16 + lr;
                    a[mt][0] = sm.off.u.p1.A[base + lk][r];
                    a[mt][1] = sm.off.u.p1.A[base + lk][r + 8];
                    a[mt][2] = sm.off.u.p1.A[base + lk + 4][r];
                    a[mt][3] = sm.off.u.p1.A[base + lk + 4][r + 8];
                }
#pragma unroll
                for (int nt = 0; nt < 2; nt++) {
                    int c = warp_n * 16 + nt * 8 + lr;
                    bf[nt][0] = sm.off.u.p1.Bq[base + lk][c];
                    bf[nt][1] = sm.off.u.p1.Bq[base + lk + 4][c];
                }
#pragma unroll
                for (int mt = 0; mt < 4; mt++)
#pragma unroll
                    for (int nt = 0; nt < 2; nt++)
                        mma_bf16(acc[mt][nt], a[mt], bf[nt]);
            }
            __syncthreads();
        }

        int lc2 = (lane & 3) * 2;
#pragma unroll
        for (int mt = 0; mt < 4; mt++) {
#pragma unroll
            for (int nt = 0; nt < 2; nt++) {
                int c = warp_n * 16 + nt * 8 + lc2;
                if (c < 48) {
                    int r = warp_m * 64 + mt * 16 + lr;
                    *(float2*)&sm.off.u.Out[r][c]     = make_float2(acc[mt][nt][0], acc[mt][nt][1]);
                    *(float2*)&sm.off.u.Out[r + 8][c] = make_float2(acc[mt][nt][2], acc[mt][nt][3]);
                }
            }
        }
        __syncthreads();

        if (tid < 128) {
            int qg = q0 + tid;
            int gidx = b * NQ + qg;
            float r = g_rstd1[gidx];
            float mterm = r * g_mean1[gidx];
            float vals[48];
#pragma unroll
            for (int j = 0; j < 48; j++)
                vals[j] = r * sm.off.u.Out[tid][j] - mterm * g_gs48[j] + g_c48[j] + g_qp[qg * 48 + j];

            float wpix = (float)(qg & 63);
            float hpix = (float)(qg >> 6);
#pragma unroll
            for (int h = 0; h < NHh; h++) {
                float* av = &vals[32 + h * 4];
                float mx = fmaxf(fmaxf(av[0], av[1]), fmaxf(av[2], av[3]));
                float e0 = __expf(av[0] - mx), e1 = __expf(av[1] - mx);
                float e2 = __expf(av[2] - mx), e3 = __expf(av[3] - mx);
                float inv = 1.0f / (e0 + e1 + e2 + e3);
                float aw[4] = {e0 * inv, e1 * inv, e2 * inv, e3 * inv};

                uint2* pp = g_pairs + ((size_t)gidx * 4 + h) * 16;
#pragma unroll
                for (int p = 0; p < NPp; p++) {
                    float px = wpix + vals[h * 8 + p * 2];
                    float py = hpix + vals[h * 8 + p * 2 + 1];
                    float fx = floorf(px), fy = floorf(py);
                    int ix = (int)fx, iy = (int)fy;
                    float wx = px - fx, wy = py - fy;
                    float a = aw[p];
                    uint4 st0, st1;
#pragma unroll
                    for (int c = 0; c < 4; c++) {
                        int cx = ix + (c & 1);
                        int cy = iy + (c >> 1);
                        bool valid = (cx >= 0) & (cx < Ww) & (cy >= 0) & (cy < Hh);
                        float wgt = valid ? ((c & 1) ? wx : 1.f - wx) * ((c >> 1) ? wy : 1.f - wy) * a : 0.f;
                        uint32_t off = valid ? (uint32_t)(cy * Ww + cx) * 512u : 0u;
                        if (c == 0) { st0.x = off; st0.y = __float_as_uint(wgt); }
                        if (c == 1) { st0.z = off; st0.w = __float_as_uint(wgt); }
                        if (c == 2) { st1.x = off; st1.y = __float_as_uint(wgt); }
                        if (c == 3) { st1.z = off; st1.w = __float_as_uint(wgt); }
                    }
                    *(uint4*)&pp[p * 4]     = st0;
                    *(uint4*)&pp[p * 4 + 2] = st1;
                }
            }
        }
    }
    PDL_TRIGGER();
}

// ---------------- K5: bilinear sampling — warp = (q, 4 heads), lane = 8 channels ----------------
__global__ void __launch_bounds__(512) k_sample()
{
    int tid = threadIdx.x;
    int warp = tid >> 5, lane = tid & 31;
    int b = blockIdx.y;
    int qg = blockIdx.x * 16 + warp;
    int head = lane >> 3;
    int grp = lane & 7;
    int gidx = b * NQ + qg;

    PDL_WAIT();

    uint4 pr = *((const uint4*)(g_pairs + ((size_t)gidx * 4 + head) * 16) + grp);

    const char* __restrict__ vbase =
        (const char*)g_value + (size_t)b * NQ * 512 + head * 128 + grp * 16;

    float a0 = 0.f, a1 = 0.f, a2 = 0.f, a3 = 0.f;
    float a4 = 0.f, a5 = 0.f, a6 = 0.f, a7 = 0.f;
#pragma unroll
    for (int c = 0; c < 16; c++) {
        int srcl = c >> 1;
        uint32_t ob = __shfl_sync(0xFFFFFFFFu, (c & 1) ? pr.z : pr.x, srcl, 8);
        float w = __uint_as_float(__shfl_sync(0xFFFFFFFFu, (c & 1) ? pr.w : pr.y, srcl, 8));
        uint4 v = *(const uint4*)(vbase + ob);
        a0 += w * __uint_as_float(v.x << 16);
        a1 += w * __uint_as_float(v.x & 0xFFFF0000u);
        a2 += w * __uint_as_float(v.y << 16);
        a3 += w * __uint_as_float(v.y & 0xFFFF0000u);
        a4 += w * __uint_as_float(v.z << 16);
        a5 += w * __uint_as_float(v.z & 0xFFFF0000u);
        a6 += w * __uint_as_float(v.w << 16);
        a7 += w * __uint_as_float(v.w & 0xFFFF0000u);
    }
    uint4 st;
    st.x = packbf(a0, a1);
    st.y = packbf(a2, a3);
    st.z = packbf(a4, a5);
    st.w = packbf(a6, a7);
    *(uint4*)((char*)g_S + (size_t)gidx * 512 + head * 128 + grp * 16) = st;
    PDL_TRIGGER();
}

// ---------------- K6: output GEMM (bf16 mma, A cp.async + B reg-pipelined), 128x128 ----------------
__global__ void __launch_bounds__(256, 2) k_gemm_out(const float* __restrict__ x2,
                                                     const float* __restrict__ b_out,
                                                     float* __restrict__ out)
{
    __shared__ uint32_t As2[2][16][136];
    __shared__ uint32_t Bs2[2][16][136];

    int b = blockIdx.z;
    int m0 = blockIdx.x * 128;      // c'
    int n0 = blockIdx.y * 128;      // q
    int tid = threadIdx.x;
    int wid = tid >> 5, lane = tid & 31;
    int warp_m = wid & 1, warp_n = wid >> 1;
    int lr = lane >> 2, lk = lane & 3;

    float acc[4][4][4];
#pragma unroll
    for (int i = 0; i < 4; i++)
#pragma unroll
        for (int j = 0; j < 4; j++)
#pragma unroll
            for (int r = 0; r < 4; r++) acc[i][j][r] = 0.f;

    const uint32_t* Sb = g_S + (size_t)(b * NQ + n0) * 128;

    int row0 = tid >> 5, seg0 = tid & 31;
    int row1 = (tid + 256) >> 5, seg1 = (tid + 256) & 31;
    int bq = tid >> 4, bk = tid & 15;

    uint32_t breg[8];

    // A stage-0 (W_out pack — written by k_pre, safely flushed 2 launches upstream)
    cp16(&As2[0][row0][seg0 * 4], g_Wob + row0 * 256 + m0 + seg0 * 4);
    cp16(&As2[0][row1][seg1 * 4], g_Wob + row1 * 256 + m0 + seg1 * 4);
    CP_COMMIT();

    PDL_WAIT();   // S (from k_sample) must be visible before B loads

#pragma unroll
    for (int i = 0; i < 8; i++)
        breg[i] = Sb[(size_t)(bq + i * 16) * 128 + bk];
#pragma unroll
    for (int i = 0; i < 8; i++)
        Bs2[0][bk][bq + i * 16] = breg[i];

    for (int it = 0; it < 8; it++) {
        if (it < 7) {
            int k2b = (it + 1) * 16;
            int s = (it + 1) & 1;
            cp16(&As2[s][row0][seg0 * 4], g_Wob + (k2b + row0) * 256 + m0 + seg0 * 4);
            cp16(&As2[s][row1][seg1 * 4], g_Wob + (k2b + row1) * 256 + m0 + seg1 * 4);
            CP_COMMIT();
#pragma unroll
            for (int i = 0; i < 8; i++)
                breg[i] = Sb[(size_t)(bq + i * 16) * 128 + k2b + bk];
            CP_WAIT1();
        } else {
            CP_WAIT0();
        }
        __syncthreads();
        int s = it & 1;
#pragma unroll
        for (int kk = 0; kk < 2; kk++) {
            int base = kk * 8;
            uint32_t a[4][4], bf[4][2];
#pragma unroll
            for (int mt = 0; mt < 4; mt++) {
                int r = warp_m * 64 + mt * 16 + lr;
                a[mt][0] = As2[s][base + lk][r];
                a[mt][1] = As2[s][base + lk][r + 8];
                a[mt][2] = As2[s][base + lk + 4][r];
                a[mt][3] = As2[s][base + lk + 4][r + 8];
            }
#pragma unroll
            for (int nt = 0; nt < 4; nt++) {
                int c = warp_n * 32 + nt * 8 + lr;
                bf[nt][0] = Bs2[s][base + lk][c];
                bf[nt][1] = Bs2[s][base + lk + 4][c];
            }
#pragma unroll
            for (int mt = 0; mt < 4; mt++)
#pragma unroll
                for (int nt = 0; nt < 4; nt++)
                    mma_bf16(acc[mt][nt], a[mt], bf[nt]);
        }
        if (it < 7) {
            int s2 = (it + 1) & 1;
#pragma unroll
            for (int i = 0; i < 8; i++)
                Bs2[s2][bk][bq + i * 16] = breg[i];
        }
        __syncthreads();
    }

    int lc2 = (lane & 3) * 2;
#pragma unroll
    for (int mt = 0; mt < 4; mt++) {
        int c1 = m0 + warp_m * 64 + mt * 16 + lr;
        int c2 = c1 + 8;
        float bo1 = b_out[c1], bo2 = b_out[c2];
        size_t base1 = ((size_t)b * Cc + c1) * NQ;
        size_t base2 = ((size_t)b * Cc + c2) * NQ;
#pragma unroll
        for (int nt = 0; nt < 4; nt++) {
            int q = n0 + warp_n * 32 + nt * 8 + lc2;
            float2 x1v = *(const float2*)(x2 + base1 + q);
            float2 x2v = *(const float2*)(x2 + base2 + q);
            float2 o1, o2;
            o1.x = acc[mt][nt][0] + bo1 + x1v.x;
            o1.y = acc[mt][nt][1] + bo1 + x1v.y;
            o2.x = acc[mt][nt][2] + bo2 + x2v.x;
            o2.y = acc[mt][nt][3] + bo2 + x2v.y;
            *(float2*)(out + base1 + q) = o1;
            *(float2*)(out + base2 + q) = o2;
        }
    }
}

// ---------------- launch ----------------
extern "C" void kernel_launch(void* const* d_in, const int* in_sizes, int n_in,
                              void* d_out, int out_size)
{
    const float* x1        = (const float*)d_in[0];
    const float* x2        = (const float*)d_in[1];
    const float* ln1_g     = (const float*)d_in[2];
    const float* ln1_b     = (const float*)d_in[3];
    const float* ln2_g     = (const float*)d_in[4];
    const float* ln2_b     = (const float*)d_in[5];
    const float* pos_scale = (const float*)d_in[6];
    const float* W_off     = (const float*)d_in[7];
    const float* b_off     = (const float*)d_in[8];
    const float* W_att     = (const float*)d_in[9];
    const float* b_att     = (const float*)d_in[10];
    const float* W_val     = (const float*)d_in[11];
    const float* b_val     = (const float*)d_in[12];
    const float* W_out     = (const float*)d_in[13];
    const float* b_out     = (const float*)d_in[14];
    float* out = (float*)d_out;

    k_pre<<<298, 256>>>(x1, x2, ln1_g, ln1_b, ln2_g, ln2_b, pos_scale,
                        W_off, b_off, W_att, b_att, W_val, b_val, W_out);

    cudaLaunchAttribute at[1];
    at[0].id = cudaLaunchAttributeProgrammaticStreamSerialization;
    at[0].val.programmaticStreamSerializationAllowed = 1;

    {
        cudaLaunchConfig_t cfg = {};
        cfg.gridDim = dim3(768, 1, 1);
        cfg.blockDim = dim3(256, 1, 1);
        cfg.attrs = at;
        cfg.numAttrs = 1;
        cudaLaunchKernelEx(&cfg, k_mid);
    }
    {
        cudaLaunchConfig_t cfg = {};
        cfg.gridDim = dim3(NQ / 16, Bb, 1);
        cfg.blockDim = dim3(512, 1, 1);
        cfg.attrs = at;
        cfg.numAttrs = 1;
        cudaLaunchKernelEx(&cfg, k_sample);
    }
    {
        cudaLaunchConfig_t cfg = {};
        cfg.gridDim = dim3(2, NQ / 128, Bb);
        cfg.blockDim = dim3(256, 1, 1);
        cfg.attrs = at;
        cfg.numAttrs = 1;
        cudaLaunchKernelEx(&cfg, k_gemm_out, x2, b_out, out);
    }
}

// round 14
// speedup vs baseline: 1.0839x; 1.0302x over previous
#include <cuda_runtime.h>
#include <cuda_bf16.h>
#include <math.h>
#include <stdint.h>

// Problem constants
#define Bb   8
#define Cc   256
#define Hh   64
#define Ww   64
#define NQ   4096           // H*W
#define NPIX (Bb*NQ)        // 32768
#define NHh  4
#define NPp  4
#define Dd   64
#define EPSf 1e-5f

// ---------------- scratch (static device globals; no allocation) ----------------
__device__ float g_mean1[NPIX], g_rstd1[NPIX], g_mean2[NPIX], g_rstd2[NPIX];
__device__ float g_qp[NQ * 48];
__device__ float g_c48[48];
__device__ float g_gs48[48];
__device__ float g_vG[Cc];
__device__ float g_vc[Cc];
__device__ uint32_t g_x1b[(size_t)NPIX * 128];
__device__ uint32_t g_x2b[(size_t)NPIX * 128];
__device__ uint32_t g_Wvb[128 * 256];
__device__ uint32_t g_Wob[128 * 256];
__device__ uint32_t g_Wqb[128 * 64];
__device__ uint32_t g_value[NPIX * Cc / 2];
__device__ uint2 g_pairs[(size_t)NPIX * 64];

// ---------------- helpers ----------------
__device__ __forceinline__ uint32_t packbf(float lo, float hi)
{
    __nv_bfloat162 h = __floats2bfloat162_rn(lo, hi);
    return *(uint32_t*)&h;
}

__device__ __forceinline__ void mma_bf16(float* d, const uint32_t* a, const uint32_t* b)
{
    asm volatile(
        "mma.sync.aligned.m16n8k16.row.col.f32.bf16.bf16.f32 "
        "{%0,%1,%2,%3}, {%4,%5,%6,%7}, {%8,%9}, {%0,%1,%2,%3};\n"
        : "+f"(d[0]), "+f"(d[1]), "+f"(d[2]), "+f"(d[3])
        : "r"(a[0]), "r"(a[1]), "r"(a[2]), "r"(a[3]), "r"(b[0]), "r"(b[1]));
}

__device__ __forceinline__ void cp16(void* smem_dst, const void* gmem_src)
{
    uint32_t sa = (uint32_t)__cvta_generic_to_shared(smem_dst);
    asm volatile("cp.async.cg.shared.global [%0], [%1], 16;\n" :: "r"(sa), "l"(gmem_src));
}
#define CP_COMMIT() asm volatile("cp.async.commit_group;\n" ::: "memory")
#define CP_WAIT1()  asm volatile("cp.async.wait_group 1;\n" ::: "memory")
#define CP_WAIT0()  asm volatile("cp.async.wait_group 0;\n" ::: "memory")

#define PDL_TRIGGER() asm volatile("griddepcontrol.launch_dependents;" ::: "memory")
#define PDL_WAIT()    asm volatile("griddepcontrol.wait;" ::: "memory")

// ---------------- K_pre ----------------
// grid: 0 = const; 1..256 = stats+x-pack; 257..288 = qp GEMM (mma);
//       289..296 = Wval/Wout pack; 297 = Wq pack
__global__ void __launch_bounds__(256) k_pre(
    const float* __restrict__ x1, const float* __restrict__ x2,
    const float* __restrict__ ln1_g, const float* __restrict__ ln1_b,
    const float* __restrict__ ln2_g, const float* __restrict__ ln2_b,
    const float* __restrict__ pos_scale,
    const float* __restrict__ W_off, const float* __restrict__ b_off,
    const float* __restrict__ W_att, const float* __restrict__ b_att,
    const float* __restrict__ W_val, const float* __restrict__ b_val,
    const float* __restrict__ W_out)
{
    int bid = blockIdx.x;
    int tid = threadIdx.x;

    if (bid == 0) {
        float sG = 0.f, sc = 0.f;
        for (int k = 0; k < Cc; k++) {
            float w = W_val[k * Cc + tid];
            sG += ln2_g[k] * w;
            sc += ln2_b[k] * w;
        }
        g_vG[tid] = sG;
        g_vc[tid] = sc + b_val[tid];

        if (tid < 48) {
            float s1 = 0.f, s2 = 0.f, bb;
            if (tid < 32) {
                for (int k = 0; k < Cc; k++) {
                    float w = W_off[k * 32 + tid];
                    s1 += ln1_b[k] * w;
                    s2 += ln1_g[k] * w;
                }
                bb = b_off[tid];
            } else {
                int j = tid - 32;
                for (int k = 0; k < Cc; k++) {
                    float w = W_att[k * 16 + j];
                    s1 += ln1_b[k] * w;
                    s2 += ln1_g[k] * w;
                }
                bb = b_att[j];
            }
            g_c48[tid] = s1 + bb;
            g_gs48[tid] = s2;
        }
    } else if (bid <= 256) {
        int t = (bid - 1) * 256 + tid;
        int idx = t & (NPIX - 1);
        int b = idx >> 12, q = idx & (NQ - 1);
        const float* p = ((t < NPIX) ? x1 : x2) + b * (Cc * NQ) + q;
        uint32_t* xb = ((t < NPIX) ? g_x1b : g_x2b) + (size_t)(b * 128) * NQ + q;
        float s = 0.f, ss = 0.f;
#pragma unroll 8
        for (int k2 = 0; k2 < 128; k2++) {
            float v0 = p[(2 * k2) * NQ];
            float v1 = p[(2 * k2 + 1) * NQ];
            s += v0 + v1;
            ss += v0 * v0 + v1 * v1;
            xb[(size_t)k2 * NQ] = packbf(v0, v1);
        }
        float m = s * (1.0f / Cc);
        float var = ss * (1.0f / Cc) - m * m;
        float r = rsqrtf(var + EPSf);
        if (t < NPIX) { g_mean1[idx] = m; g_rstd1[idx] = r; }
        else          { g_mean2[idx] = m; g_rstd2[idx] = r; }
    } else if (bid <= 288) {
        __shared__ float invf_s[128];
        __shared__ uint32_t Aq[16][136];
        __shared__ uint32_t Bq[16][72];

        int q0 = (bid - 257) * 128;
        float ps = pos_scale[0];
        if (tid < 128)
            invf_s[tid] = expf(-9.210340371976184f * (float)tid * (1.0f / 128.0f));
        __syncthreads();

        int wid = tid >> 5, lane = tid & 31;
        int warp_m = wid & 1, warp_n = wid >> 1;
        int lr = lane >> 2, lk = lane & 3;

        float acc[4][2][4];
#pragma unroll
        for (int i = 0; i < 4; i++)
#pragma unroll
            for (int j = 0; j < 2; j++)
#pragma unroll
                for (int r = 0; r < 4; r++) acc[i][j][r] = 0.f;

        for (int k0 = 0; k0 < Cc; k0 += 32) {
#pragma unroll
            for (int i = 0; i < 8; i++) {
                int lin = tid + i * 256;
                int k2 = lin >> 7;
                int q = lin & 127;
                int k = k0 + 2 * k2;
                float fq = (float)(q0 + q);
                float v0 = (k < 128) ? sinf(fq * invf_s[k]) : cosf(fq * invf_s[k - 128]);
                float v1 = (k + 1 < 128) ? sinf(fq * invf_s[k + 1]) : cosf(fq * invf_s[k - 127]);
                Aq[k2][q] = packbf(v0 * ps, v1 * ps);
            }
#pragma unroll
            for (int i = 0; i < 4; i++) {
                int lin = tid + i * 256;
                int j = lin & 63;
                int k2 = lin >> 6;
                int k = k0 + 2 * k2;
                float lo = 0.f, hi = 0.f;
                if (j < 32) {
                    lo = W_off[k * 32 + j];
                    hi = W_off[(k + 1) * 32 + j];
                } else if (j < 48) {
                    int jj = j - 32;
                    lo = W_att[k * 16 + jj];
                    hi = W_att[(k + 1) * 16 + jj];
                }
                Bq[k2][j] = packbf(lo, hi);
            }
            __syncthreads();
#pragma unroll
            for (int kk = 0; kk < 2; kk++) {
                int base = kk * 8;
                uint32_t a[4][4], bf[2][2];
#pragma unroll
                for (int mt = 0; mt < 4; mt++) {
                    int r = warp_m * 64 + mt * 16 + lr;
                    a[mt][0] = Aq[base + lk][r];
                    a[mt][1] = Aq[base + lk][r + 8];
                    a[mt][2] = Aq[base + lk + 4][r];
                    a[mt][3] = Aq[base + lk + 4][r + 8];
                }
#pragma unroll
                for (int nt = 0; nt < 2; nt++) {
                    int c = warp_n * 16 + nt * 8 + lr;
                    bf[nt][0] = Bq[base + lk][c];
                    bf[nt][1] = Bq[base + lk + 4][c];
                }
#pragma unroll
                for (int mt = 0; mt < 4; mt++)
#pragma unroll
                    for (int nt = 0; nt < 2; nt++)
                        mma_bf16(acc[mt][nt], a[mt], bf[nt]);
            }
            __syncthreads();
        }

        int lc2 = (lane & 3) * 2;
#pragma unroll
        for (int mt = 0; mt < 4; mt++) {
#pragma unroll
            for (int nt = 0; nt < 2; nt++) {
                int c = warp_n * 16 + nt * 8 + lc2;
                if (c < 48) {
                    int r1 = q0 + warp_m * 64 + mt * 16 + lr;
                    *(float2*)&g_qp[r1 * 48 + c] = make_float2(acc[mt][nt][0], acc[mt][nt][1]);
                    *(float2*)&g_qp[(r1 + 8) * 48 + c] = make_float2(acc[mt][nt][2], acc[mt][nt][3]);
                }
            }
        }
    } else if (bid <= 296) {
        int wb = bid - 289;
        if (wb < 4) {
#pragma unroll 4
            for (int r = 0; r < 32; r++) {
                int k2 = wb * 32 + r;
                int k = 2 * k2;
                float g0 = ln2_g[k], g1 = ln2_g[k + 1];
                g_Wvb[k2 * 256 + tid] = packbf(W_val[k * 256 + tid] * g0,
                                               W_val[(k + 1) * 256 + tid] * g1);
            }
        } else {
#pragma unroll 4
            for (int r = 0; r < 32; r++) {
                int k2 = (wb - 4) * 32 + r;
                int k = 2 * k2;
                g_Wob[k2 * 256 + tid] = packbf(W_out[k * 256 + tid],
                                               W_out[(k + 1) * 256 + tid]);
            }
        }
    } else {
#pragma unroll 4
        for (int i = 0; i < 32; i++) {
            int lin = i * 256 + tid;
            int k2 = lin >> 6, j = lin & 63;
            int k = 2 * k2;
            float lo = 0.f, hi = 0.f;
            if (j < 32) {
                lo = W_off[k * 32 + j] * ln1_g[k];
                hi = W_off[(k + 1) * 32 + j] * ln1_g[k + 1];
            } else if (j < 48) {
                int jj = j - 32;
                lo = W_att[k * 16 + jj] * ln1_g[k];
                hi = W_att[(k + 1) * 16 + jj] * ln1_g[k + 1];
            }
            g_Wqb[k2 * 64 + j] = packbf(lo, hi);
        }
    }
    PDL_TRIGGER();
}

// ---------------- K_mid: merged value-GEMM (bids 0..511) + off/att GEMM (bids 512..767) ----------------
union SmemMid {
    struct { uint32_t A[2][16][136]; uint32_t B[2][16][136]; } val;
    struct {
        union {
            struct { uint32_t A[16][136]; uint32_t Bq[16][72]; } p1;
            float Out[128][52];
        } u;
    } off;
};

__global__ void __launch_bounds__(256, 2) k_mid()
{
    __shared__ SmemMid sm;
    int bid = blockIdx.x;
    int tid = threadIdx.x;
    int wid = tid >> 5, lane = tid & 31;
    int lr = lane >> 2, lk = lane & 3;

    PDL_WAIT();

    if (bid < 512) {
        int v = bid;
        int b = v >> 6;
        int m0 = ((v >> 1) & 31) * 128;
        int n0 = (v & 1) * 128;
        int warp_m = wid & 1, warp_n = wid >> 1;

        float acc[4][4][4];
#pragma unroll
        for (int i = 0; i < 4; i++)
#pragma unroll
            for (int j = 0; j < 4; j++)
#pragma unroll
                for (int r = 0; r < 4; r++) acc[i][j][r] = 0.f;

        const uint32_t* Ab = g_x2b + (size_t)(b * 128) * NQ + m0;

        int row0 = tid >> 5, seg0 = tid & 31;
        int row1 = (tid + 256) >> 5, seg1 = (tid + 256) & 31;

        cp16(&sm.val.A[0][row0][seg0 * 4], Ab + (size_t)row0 * NQ + seg0 * 4);
        cp16(&sm.val.A[0][row1][seg1 * 4], Ab + (size_t)row1 * NQ + seg1 * 4);
        cp16(&sm.val.B[0][row0][seg0 * 4], g_Wvb + row0 * 256 + n0 + seg0 * 4);
        cp16(&sm.val.B[0][row1][seg1 * 4], g_Wvb + row1 * 256 + n0 + seg1 * 4);
        CP_COMMIT();

        for (int it = 0; it < 8; it++) {
            if (it < 7) {
                int k2b = (it + 1) * 16;
                int s = (it + 1) & 1;
                cp16(&sm.val.A[s][row0][seg0 * 4], Ab + (size_t)(k2b + row0) * NQ + seg0 * 4);
                cp16(&sm.val.A[s][row1][seg1 * 4], Ab + (size_t)(k2b + row1) * NQ + seg1 * 4);
                cp16(&sm.val.B[s][row0][seg0 * 4], g_Wvb + (k2b + row0) * 256 + n0 + seg0 * 4);
                cp16(&sm.val.B[s][row1][seg1 * 4], g_Wvb + (k2b + row1) * 256 + n0 + seg1 * 4);
                CP_COMMIT();
                CP_WAIT1();
            } else {
                CP_WAIT0();
            }
            __syncthreads();
            int s = it & 1;
#pragma unroll
            for (int kk = 0; kk < 2; kk++) {
                int base = kk * 8;
                uint32_t a[4][4], bf[4][2];
#pragma unroll
                for (int mt = 0; mt < 4; mt++) {
                    int r = warp_m * 64 + mt * 16 + lr;
                    a[mt][0] = sm.val.A[s][base + lk][r];
                    a[mt][1] = sm.val.A[s][base + lk][r + 8];
                    a[mt][2] = sm.val.A[s][base + lk + 4][r];
                    a[mt][3] = sm.val.A[s][base + lk + 4][r + 8];
                }
#pragma unroll
                for (int nt = 0; nt < 4; nt++) {
                    int c = warp_n * 32 + nt * 8 + lr;
                    bf[nt][0] = sm.val.B[s][base + lk][c];
                    bf[nt][1] = sm.val.B[s][base + lk + 4][c];
                }
#pragma unroll
                for (int mt = 0; mt < 4; mt++)
#pragma unroll
                    for (int nt = 0; nt < 4; nt++)
                        mma_bf16(acc[mt][nt], a[mt], bf[nt]);
            }
            __syncthreads();
        }

        int lc2 = (lane & 3) * 2;
#pragma unroll
        for (int mt = 0; mt < 4; mt++) {
            int q1 = m0 + warp_m * 64 + mt * 16 + lr;
            int q2 = q1 + 8;
            int g1 = b * NQ + q1, g2 = b * NQ + q2;
            float r1 = g_rstd2[g1], mm1 = r1 * g_mean2[g1];
            float r2 = g_rstd2[g2], mm2 = r2 * g_mean2[g2];
#pragma unroll
            for (int nt = 0; nt < 4; nt++) {
                int c = n0 + warp_n * 32 + nt * 8 + lc2;
                float vG0 = g_vG[c], vG1 = g_vG[c + 1];
                float vc0 = g_vc[c], vc1 = g_vc[c + 1];
                g_value[(size_t)g1 * 128 + (c >> 1)] =
                    packbf(r1 * acc[mt][nt][0] - mm1 * vG0 + vc0,
                           r1 * acc[mt][nt][1] - mm1 * vG1 + vc1);
                g_value[(size_t)g2 * 128 + (c >> 1)] =
                    packbf(r2 * acc[mt][nt][2] - mm2 * vG0 + vc0,
                           r2 * acc[mt][nt][3] - mm2 * vG1 + vc1);
            }
        }
    } else {
        int o = bid - 512;
        int b = o >> 5;
        int q0 = (o & 31) * 128;
        int warp_m = wid & 1, warp_n = wid >> 1;

        float acc[4][2][4];
#pragma unroll
        for (int i = 0; i < 4; i++)
#pragma unroll
            for (int j = 0; j < 2; j++)
#pragma unroll
                for (int r = 0; r < 4; r++) acc[i][j][r] = 0.f;

        const uint32_t* Ab = g_x1b + (size_t)(b * 128) * NQ + q0;

        for (int k0 = 0; k0 < Cc; k0 += 32) {
            int k2b = k0 >> 1;
#pragma unroll
            for (int i = 0; i < 2; i++) {
                int lin = tid + i * 256;
                int row = lin >> 5, seg = lin & 31;
                *(uint4*)&sm.off.u.p1.A[row][seg * 4] =
                    *(const uint4*)(Ab + (size_t)(k2b + row) * NQ + seg * 4);
            }
            {
                int row = tid >> 4, seg = tid & 15;
                *(uint4*)&sm.off.u.p1.Bq[row][seg * 4] =
                    *(const uint4*)(g_Wqb + (k2b + row) * 64 + seg * 4);
            }
            __syncthreads();
#pragma unroll
            for (int kk = 0; kk < 2; kk++) {
                int base = kk * 8;
                uint32_t a[4][4], bf[2][2];
#pragma unroll
                for (int mt = 0; mt < 4; mt++) {
                    int r = warp_m * 64 + mt * 16 + lr;
                    a[mt][0] = sm.off.u.p1.A[base + lk][r];
                    a[mt][1] = sm.off.u.p1.A[base + lk][r + 8];
                    a[mt][2] = sm.off.u.p1.A[base + lk + 4][r];
                    a[mt][3] = sm.off.u.p1.A[base + lk + 4][r + 8];
                }
#pragma unroll
                for (int nt = 0; nt < 2; nt++) {
                    int c = warp_n * 16 + nt * 8 + lr;
                    bf[nt][0] = sm.off.u.p1.Bq[base + lk][c];
                    bf[nt][1] = sm.off.u.p1.Bq[base + lk + 4][c];
                }
#pragma unroll
                for (int mt = 0; mt < 4; mt++)
#pragma unroll
                    for (int nt = 0; nt < 2; nt++)
                        mma_bf16(acc[mt][nt], a[mt], bf[nt]);
            }
            __syncthreads();
        }

        int lc2 = (lane & 3) * 2;
#pragma unroll
        for (int mt = 0; mt < 4; mt++) {
#pragma unroll
            for (int nt = 0; nt < 2; nt++) {
                int c = warp_n * 16 + nt * 8 + lc2;
                if (c < 48) {
                    int r = warp_m * 64 + mt * 16 + lr;
                    *(float2*)&sm.off.u.Out[r][c]     = make_float2(acc[mt][nt][0], acc[mt][nt][1]);
                    *(float2*)&sm.off.u.Out[r + 8][c] = make_float2(acc[mt][nt][2], acc[mt][nt][3]);
                }
            }
        }
        __syncthreads();

        if (tid < 128) {
            int qg = q0 + tid;
            int gidx = b * NQ + qg;
            float r = g_rstd1[gidx];
            float mterm = r * g_mean1[gidx];
            float vals[48];
#pragma unroll
            for (int j = 0; j < 48; j++)
                vals[j] = r * sm.off.u.Out[tid][j] - mterm * g_gs48[j] + g_c48[j] + g_qp[qg * 48 + j];

            float wpix = (float)(qg & 63);
            float hpix = (float)(qg >> 6);
#pragma unroll
            for (int h = 0; h < NHh; h++) {
                float* av = &vals[32 + h * 4];
                float mx = fmaxf(fmaxf(av[0], av[1]), fmaxf(av[2], av[3]));
                float e0 = __expf(av[0] - mx), e1 = __expf(av[1] - mx);
                float e2 = __expf(av[2] - mx), e3 = __expf(av[3] - mx);
                float inv = 1.0f / (e0 + e1 + e2 + e3);
                float aw[4] = {e0 * inv, e1 * inv, e2 * inv, e3 * inv};

                uint2* pp = g_pairs + ((size_t)gidx * 4 + h) * 16;
#pragma unroll
                for (int p = 0; p < NPp; p++) {
                    float px = wpix + vals[h * 8 + p * 2];
                    float py = hpix + vals[h * 8 + p * 2 + 1];
                    float fx = floorf(px), fy = floorf(py);
                    int ix = (int)fx, iy = (int)fy;
                    float wx = px - fx, wy = py - fy;
                    float a = aw[p];
                    uint4 st0, st1;
#pragma unroll
                    for (int c = 0; c < 4; c++) {
                        int cx = ix + (c & 1);
                        int cy = iy + (c >> 1);
                        bool valid = (cx >= 0) & (cx < Ww) & (cy >= 0) & (cy < Hh);
                        float wgt = valid ? ((c & 1) ? wx : 1.f - wx) * ((c >> 1) ? wy : 1.f - wy) * a : 0.f;
                        uint32_t off = valid ? (uint32_t)(cy * Ww + cx) * 512u : 0u;
                        if (c == 0) { st0.x = off; st0.y = __float_as_uint(wgt); }
                        if (c == 1) { st0.z = off; st0.w = __float_as_uint(wgt); }
                        if (c == 2) { st1.x = off; st1.y = __float_as_uint(wgt); }
                        if (c == 3) { st1.z = off; st1.w = __float_as_uint(wgt); }
                    }
                    *(uint4*)&pp[p * 4]     = st0;
                    *(uint4*)&pp[p * 4 + 2] = st1;
                }
            }
        }
    }
    PDL_TRIGGER();
}

// ---------------- K_out2: fused sampling + output GEMM ----------------
// CTA = 256(m=c') x 64(q); 8 warps (4 warp_m x 2 warp_n), warp tile 64x32
__global__ void __launch_bounds__(256, 2) k_out2(const float* __restrict__ x2,
                                                 const float* __restrict__ b_out,
                                                 float* __restrict__ out)
{
    __shared__ uint32_t Ssm[64][132];       // sampled S: [q][k2]
    __shared__ uint32_t As2[2][16][264];    // W_out pack: [k2][m]

    int b = blockIdx.y;
    int n0 = blockIdx.x * 64;
    int tid = threadIdx.x;
    int wid = tid >> 5, lane = tid & 31;

    // A stage-0 prologue (depends only on k_pre, flushed 2 launches back)
#pragma unroll
    for (int i = 0; i < 4; i++) {
        int lin = tid + i * 256;            // 1024 uint4
        int row = lin >> 6, seg = lin & 63;
        cp16(&As2[0][row][seg * 4], g_Wob + row * 256 + seg * 4);
    }
    CP_COMMIT();

    PDL_WAIT();

    // ---- phase 1: sample this CTA's 64 queries into Ssm ----
    {
        int head = lane >> 3;
        int grp = lane & 7;
        const char* __restrict__ vbase =
            (const char*)g_value + (size_t)b * NQ * 512 + head * 128 + grp * 16;
        for (int qi = 0; qi < 8; qi++) {
            int ql = wid * 8 + qi;
            int gidx = b * NQ + n0 + ql;
            uint4 pr = *((const uint4*)(g_pairs + ((size_t)gidx * 4 + head) * 16) + grp);
            float a0 = 0.f, a1 = 0.f, a2 = 0.f, a3 = 0.f;
            float a4 = 0.f, a5 = 0.f, a6 = 0.f, a7 = 0.f;
#pragma unroll
            for (int c = 0; c < 16; c++) {
                int srcl = c >> 1;
                uint32_t ob = __shfl_sync(0xFFFFFFFFu, (c & 1) ? pr.z : pr.x, srcl, 8);
                float w = __uint_as_float(__shfl_sync(0xFFFFFFFFu, (c & 1) ? pr.w : pr.y, srcl, 8));
                uint4 v = *(const uint4*)(vbase + ob);
                a0 += w * __uint_as_float(v.x << 16);
                a1 += w * __uint_as_float(v.x & 0xFFFF0000u);
                a2 += w * __uint_as_float(v.y << 16);
                a3 += w * __uint_as_float(v.y & 0xFFFF0000u);
                a4 += w * __uint_as_float(v.z << 16);
                a5 += w * __uint_as_float(v.z & 0xFFFF0000u);
                a6 += w * __uint_as_float(v.w << 16);
                a7 += w * __uint_as_float(v.w & 0xFFFF0000u);
            }
            uint4 st;
            st.x = packbf(a0, a1);
            st.y = packbf(a2, a3);
            st.z = packbf(a4, a5);
            st.w = packbf(a6, a7);
            *(uint4*)&Ssm[ql][head * 32 + grp * 4] = st;
        }
    }
    __syncthreads();

    // ---- phase 2: out-GEMM 256(m) x 64(q) x 256(k) ----
    int warp_m = wid & 3, warp_n = wid >> 2;
    int lr = lane >> 2, lk = lane & 3;

    float acc[4][4][4];
#pragma unroll
    for (int i = 0; i < 4; i++)
#pragma unroll
        for (int j = 0; j < 4; j++)
#pragma unroll
            for (int r = 0; r < 4; r++) acc[i][j][r] = 0.f;

    for (int it = 0; it < 8; it++) {
        if (it < 7) {
            int k2b = (it + 1) * 16;
            int s = (it + 1) & 1;
#pragma unroll
            for (int i = 0; i < 4; i++) {
                int lin = tid + i * 256;
                int row = lin >> 6, seg = lin & 63;
                cp16(&As2[s][row][seg * 4], g_Wob + (k2b + row) * 256 + seg * 4);
            }
            CP_COMMIT();
            CP_WAIT1();
        } else {
            CP_WAIT0();
        }
        __syncthreads();
        int s = it & 1;
        int k2g = it * 16;
#pragma unroll
        for (int kk = 0; kk < 2; kk++) {
            int base = kk * 8;
            uint32_t a[4][4], bf[4][2];
#pragma unroll
            for (int mt = 0; mt < 4; mt++) {
                int r = warp_m * 64 + mt * 16 + lr;
                a[mt][0] = As2[s][base + lk][r];
                a[mt][1] = As2[s][base + lk][r + 8];
                a[mt][2] = As2[s][base + lk + 4][r];
                a[mt][3] = As2[s][base + lk + 4][r + 8];
            }
#pragma unroll
            for (int nt = 0; nt < 4; nt++) {
                int c = warp_n * 32 + nt * 8 + lr;
                bf[nt][0] = Ssm[c][k2g + base + lk];
                bf[nt][1] = Ssm[c][k2g + base + lk + 4];
            }
#pragma unroll
            for (int mt = 0; mt < 4; mt++)
#pragma unroll
                for (int nt = 0; nt < 4; nt++)
                    mma_bf16(acc[mt][nt], a[mt], bf[nt]);
        }
        __syncthreads();
    }

    // epilogue: + b_out + x2 residual (fp32, (B,C,H,W))
    int lc2 = (lane & 3) * 2;
#pragma unroll
    for (int mt = 0; mt < 4; mt++) {
        int c1 = warp_m * 64 + mt * 16 + lr;
        int c2 = c1 + 8;
        float bo1 = b_out[c1], bo2 = b_out[c2];
        size_t base1 = ((size_t)b * Cc + c1) * NQ;
        size_t base2 = ((size_t)b * Cc + c2) * NQ;
#pragma unroll
        for (int nt = 0; nt < 4; nt++) {
            int q = n0 + warp_n * 32 + nt * 8 + lc2;
            float2 x1v = *(const float2*)(x2 + base1 + q);
            float2 x2v = *(const float2*)(x2 + base2 + q);
            float2 o1, o2;
            o1.x = acc[mt][nt][0] + bo1 + x1v.x;
            o1.y = acc[mt][nt][1] + bo1 + x1v.y;
            o2.x = acc[mt][nt][2] + bo2 + x2v.x;
            o2.y = acc[mt][nt][3] + bo2 + x2v.y;
            *(float2*)(out + base1 + q) = o1;
            *(float2*)(out + base2 + q) = o2;
        }
    }
}

// ---------------- launch ----------------
extern "C" void kernel_launch(void* const* d_in, const int* in_sizes, int n_in,
                              void* d_out, int out_size)
{
    const float* x1        = (const float*)d_in[0];
    const float* x2        = (const float*)d_in[1];
    const float* ln1_g     = (const float*)d_in[2];
    const float* ln1_b     = (const float*)d_in[3];
    const float* ln2_g     = (const float*)d_in[4];
    const float* ln2_b     = (const float*)d_in[5];
    const float* pos_scale = (const float*)d_in[6];
    const float* W_off     = (const float*)d_in[7];
    const float* b_off     = (const float*)d_in[8];
    const float* W_att     = (const float*)d_in[9];
    const float* b_att     = (const float*)d_in[10];
    const float* W_val     = (const float*)d_in[11];
    const float* b_val     = (const float*)d_in[12];
    const float* W_out     = (const float*)d_in[13];
    const float* b_out     = (const float*)d_in[14];
    float* out = (float*)d_out;

    k_pre<<<298, 256>>>(x1, x2, ln1_g, ln1_b, ln2_g, ln2_b, pos_scale,
                        W_off, b_off, W_att, b_att, W_val, b_val, W_out);

    cudaLaunchAttribute at[1];
    at[0].id = cudaLaunchAttributeProgrammaticStreamSerialization;
    at[0].val.programmaticStreamSerializationAllowed = 1;

    {
        cudaLaunchConfig_t cfg = {};
        cfg.gridDim = dim3(768, 1, 1);
        cfg.blockDim = dim3(256, 1, 1);
        cfg.attrs = at;
        cfg.numAttrs = 1;
        cudaLaunchKernelEx(&cfg, k_mid);
    }
    {
        cudaLaunchConfig_t cfg = {};
        cfg.gridDim = dim3(NQ / 64, Bb, 1);
        cfg.blockDim = dim3(256, 1, 1);
        cfg.attrs = at;
        cfg.numAttrs = 1;
        cudaLaunchKernelEx(&cfg, k_out2, x2, b_out, out);
    }
}